// round 9
// baseline (speedup 1.0000x reference)
#include <cuda_runtime.h>
#include <cuda_fp16.h>
#include <cuda_bf16.h>

#define NUM_USERS 100000
#define NUM_ITEMS 50000
#define DIM 64
#define N_TOTAL (NUM_USERS + NUM_ITEMS)
#define NNZ 4800000
#define TOT (N_TOTAL * DIM)

#define SCAN_CHUNK 1024
#define NCHUNK ((N_TOTAL + SCAN_CHUNK - 1) / SCAN_CHUNK)   // 147
#define GRID_ELEM ((TOT / 4 + 255) / 256)                   // 9375
#define GRID_EDGE ((NNZ + 255) / 256)                       // 18750

// fp16 layer embeddings (gather operands AND epilogue inputs)
__device__ __align__(16) __half g_h0[TOT];
__device__ __align__(16) __half g_h1[TOT];
__device__ __align__(16) __half g_h2[TOT];

// CSR build scratch
__device__ int g_cnt[N_TOTAL];            // zero at load; re-zeroed by lg_scan each call
__device__ int g_rowptr[N_TOTAL + 1];
__device__ int g_ofs[N_TOTAL];
__device__ unsigned long long g_state[NCHUNK];  // decoupled-lookback state
__device__ __align__(8) int2 g_cv[NNZ];   // .x = col, .y = val bits (fp32)

// ---------------------------------------------------------------------------
// fused init + hist. Blocks [0, GRID_ELEM): h0 = fp16(concat(ue,ie)), zero
// lookback state. Blocks [GRID_ELEM, GRID_ELEM+GRID_EDGE): row histogram.
// g_cnt is guaranteed zero at entry (load-time zero / re-zeroed by lg_scan).
// ---------------------------------------------------------------------------
__global__ void __launch_bounds__(256) lg_init_hist(const float* __restrict__ ue,
                                                    const float* __restrict__ ie,
                                                    const int* __restrict__ rows) {
    if (blockIdx.x < GRID_ELEM) {
        int i = blockIdx.x * blockDim.x + threadIdx.x;
        if (blockIdx.x == 0 && threadIdx.x < NCHUNK) g_state[threadIdx.x] = 0ULL;
        if (i >= TOT / 4) return;
        const int user4 = (NUM_USERS * DIM) / 4;
        float4 v = (i < user4) ? __ldg((const float4*)ue + i)
                               : __ldg((const float4*)ie + (i - user4));
        __half2 h01 = __float22half2_rn(make_float2(v.x, v.y));
        __half2 h23 = __float22half2_rn(make_float2(v.z, v.w));
        uint2 packed = make_uint2(*(unsigned*)&h01, *(unsigned*)&h23);
        ((uint2*)g_h0)[i] = packed;
    } else {
        int e = (blockIdx.x - GRID_ELEM) * blockDim.x + threadIdx.x;
        if (e >= NNZ) return;
        atomicAdd(&g_cnt[__ldcs(rows + e)], 1);
    }
}

// ---------------------------------------------------------------------------
// Single-kernel exclusive scan of g_cnt via decoupled lookback.
// 147 blocks x 1024 threads = one wave on 148 SMs => spin-wait is safe.
// state word: (status << 32) | value ; status 1 = aggregate, 2 = incl prefix.
// Also re-zeroes g_cnt for the next call.
// ---------------------------------------------------------------------------
__global__ void __launch_bounds__(SCAN_CHUNK) lg_scan() {
    __shared__ int ws[32];
    __shared__ int s_excl;
    const int bid = blockIdx.x;
    const int tid = threadIdx.x, lane = tid & 31, w = tid >> 5;
    const int i = bid * SCAN_CHUNK + tid;

    int v = (i < N_TOTAL) ? g_cnt[i] : 0;
    if (i < N_TOTAL) g_cnt[i] = 0;              // restore invariant for next call

    // block-local inclusive scan
    int inc = v;
    #pragma unroll
    for (int d = 1; d < 32; d <<= 1) {
        int t = __shfl_up_sync(0xffffffffu, inc, d);
        if (lane >= d) inc += t;
    }
    if (lane == 31) ws[w] = inc;
    __syncthreads();
    if (w == 0) {
        int s = ws[lane];
        #pragma unroll
        for (int d = 1; d < 32; d <<= 1) {
            int t = __shfl_up_sync(0xffffffffu, s, d);
            if (lane >= d) s += t;
        }
        ws[lane] = s;
    }
    __syncthreads();
    int total = ws[31];                          // block aggregate

    // warp 0: publish aggregate, then windowed lookback
    if (w == 0) {
        if (bid == 0) {
            if (lane == 0) {
                s_excl = 0;
                atomicExch(&g_state[0], (2ULL << 32) | (unsigned)total);
            }
        } else {
            if (lane == 0)
                atomicExch(&g_state[bid], (1ULL << 32) | (unsigned)total);
            int run = 0;
            int j = bid - 1;
            for (;;) {
                int idx = j - lane;
                unsigned long long st = (idx >= 0)
                    ? atomicAdd(&g_state[idx], 0ULL)
                    : (2ULL << 32);              // virtual block: prefix 0
                unsigned status = (unsigned)(st >> 32);
                if (__any_sync(0xffffffffu, status == 0)) continue;   // retry window
                unsigned mask2 = __ballot_sync(0xffffffffu, status == 2);
                if (mask2) {
                    int firstLane = __ffs(mask2) - 1;      // nearest prefix
                    int contrib = (lane <= firstLane) ? (int)(unsigned)st : 0;
                    #pragma unroll
                    for (int d = 16; d > 0; d >>= 1)
                        contrib += __shfl_down_sync(0xffffffffu, contrib, d);
                    contrib = __shfl_sync(0xffffffffu, contrib, 0);
                    run += contrib;
                    break;
                } else {
                    int contrib = (int)(unsigned)st;
                    #pragma unroll
                    for (int d = 16; d > 0; d >>= 1)
                        contrib += __shfl_down_sync(0xffffffffu, contrib, d);
                    contrib = __shfl_sync(0xffffffffu, contrib, 0);
                    run += contrib;
                    j -= 32;
                }
            }
            if (lane == 0) {
                s_excl = run;
                atomicExch(&g_state[bid], (2ULL << 32) | (unsigned)(run + total));
            }
        }
    }
    __syncthreads();

    int excl = inc - v + (w > 0 ? ws[w - 1] : 0) + s_excl;
    if (i < N_TOTAL) { g_rowptr[i] = excl; g_ofs[i] = excl; }
    if (bid == 0 && tid == 0) g_rowptr[N_TOTAL] = NNZ;
}

// ---------------------------------------------------------------------------
// scatter: 2 edges per thread (int2 streamed loads, MLP=2 on atomic chain)
// ---------------------------------------------------------------------------
__global__ void __launch_bounds__(256) lg_scatter(const int* __restrict__ rows,
                                                  const int* __restrict__ cols,
                                                  const float* __restrict__ vals) {
    int t = blockIdx.x * blockDim.x + threadIdx.x;
    if (t >= NNZ / 2) return;
    int2   r = __ldcs((const int2*)rows + t);
    int2   c = __ldcs((const int2*)cols + t);
    float2 v = __ldcs((const float2*)vals + t);
    int pos0 = atomicAdd(&g_ofs[r.x], 1);
    int pos1 = atomicAdd(&g_ofs[r.y], 1);
    __stcs(&g_cv[pos0], make_int2(c.x, __float_as_int(v.x)));
    __stcs(&g_cv[pos1], make_int2(c.y, __float_as_int(v.y)));
}

// ---------------------------------------------------------------------------
// CSR SpMM core: fp16 gather, fp32 accumulate. Lane l owns floats [2l, 2l+1].
// ---------------------------------------------------------------------------
__device__ __forceinline__ void spmm_batch8(const __half2* __restrict__ xh,
                                            int2 ed, int k0, int lane,
                                            float& ax, float& ay) {
    int cc[8]; float vv[8]; __half2 xv[8];
    #pragma unroll
    for (int k = 0; k < 8; k++) {
        cc[k] = __shfl_sync(0xffffffffu, ed.x, k0 + k);
        vv[k] = __int_as_float(__shfl_sync(0xffffffffu, ed.y, k0 + k));
    }
    #pragma unroll
    for (int k = 0; k < 8; k++)
        xv[k] = __ldg(xh + (size_t)cc[k] * 32 + lane);
    #pragma unroll
    for (int k = 0; k < 8; k++) {
        float2 xf = __half22float2(xv[k]);
        ax = fmaf(vv[k], xf.x, ax);
        ay = fmaf(vv[k], xf.y, ay);
    }
}

__device__ __forceinline__ void spmm_row(const __half2* __restrict__ xh,
                                         int beg, int end, int lane,
                                         float& ax, float& ay) {
    int deg = end - beg;
    int full_end = beg + (deg & ~31);
    for (int j = beg; j < full_end; j += 32) {
        int2 ed = __ldcs(g_cv + j + lane);
        #pragma unroll
        for (int k0 = 0; k0 < 32; k0 += 8)
            spmm_batch8(xh, ed, k0, lane, ax, ay);
    }
    int m = end - full_end;
    if (m > 0) {
        int jj = full_end + lane;
        int2 ed = (jj < end) ? __ldcs(g_cv + jj) : make_int2(0, 0);
        #pragma unroll
        for (int k0 = 0; k0 < 32; k0 += 8) {
            if (k0 >= m) break;
            int cc[8]; float vv[8]; __half2 xv[8];
            #pragma unroll
            for (int k = 0; k < 8; k++) {
                int src = k0 + k;
                int   c = __shfl_sync(0xffffffffu, ed.x, src);
                float v = __int_as_float(__shfl_sync(0xffffffffu, ed.y, src));
                bool ok = (src < m);
                cc[k] = ok ? c : 0;
                vv[k] = ok ? v : 0.f;
            }
            #pragma unroll
            for (int k = 0; k < 8; k++)
                xv[k] = __ldg(xh + (size_t)cc[k] * 32 + lane);
            #pragma unroll
            for (int k = 0; k < 8; k++) {
                float2 xf = __half22float2(xv[k]);
                ax = fmaf(vv[k], xf.x, ax);
                ay = fmaf(vv[k], xf.y, ay);
            }
        }
    }
}

// yh = fp16(A @ x), x fp16
__global__ void __launch_bounds__(256) lg_csr_spmm(const __half2* __restrict__ xh,
                                                   __half2* __restrict__ yh) {
    int gtid = blockIdx.x * blockDim.x + threadIdx.x;
    int row  = gtid >> 5;
    int lane = gtid & 31;
    if (row >= N_TOTAL) return;
    int beg = __ldg(g_rowptr + row);
    int end = __ldg(g_rowptr + row + 1);
    float ax = 0.f, ay = 0.f;
    spmm_row(xh, beg, end, lane, ax, ay);
    yh[(size_t)row * 32 + lane] = __float22half2_rn(make_float2(ax, ay));
}

// Layer 3 fused with the mean: out = 0.25 * (h0 + h1 + h2 + A@h2)
__global__ void __launch_bounds__(256) lg_csr_spmm_final(float* __restrict__ out) {
    int gtid = blockIdx.x * blockDim.x + threadIdx.x;
    int row  = gtid >> 5;
    int lane = gtid & 31;
    if (row >= N_TOTAL) return;
    int beg = __ldg(g_rowptr + row);
    int end = __ldg(g_rowptr + row + 1);
    float ax = 0.f, ay = 0.f;
    spmm_row((const __half2*)g_h2, beg, end, lane, ax, ay);
    size_t p = (size_t)row * 32 + lane;
    float2 e0 = __half22float2(((const __half2*)g_h0)[p]);
    float2 e1 = __half22float2(((const __half2*)g_h1)[p]);
    float2 e2 = __half22float2(((const __half2*)g_h2)[p]);
    float2 o = make_float2((e0.x + e1.x + e2.x + ax) * 0.25f,
                           (e0.y + e1.y + e2.y + ay) * 0.25f);
    ((float2*)(out + (size_t)row * DIM))[lane] = o;
}

extern "C" void kernel_launch(void* const* d_in, const int* in_sizes, int n_in,
                              void* d_out, int out_size) {
    const float* ue   = (const float*)d_in[0];
    const float* ie   = (const float*)d_in[1];
    const float* vals = (const float*)d_in[2];
    const int*   rows = (const int*)  d_in[3];
    const int*   cols = (const int*)  d_in[4];
    float* out = (float*)d_out;

    __half2 *h0, *h1, *h2;
    cudaGetSymbolAddress((void**)&h0, g_h0);
    cudaGetSymbolAddress((void**)&h1, g_h1);
    cudaGetSymbolAddress((void**)&h2, g_h2);

    const int TPB = 256;
    const int grid_rows = (N_TOTAL * 32 + TPB - 1) / TPB;

    lg_init_hist<<<GRID_ELEM + GRID_EDGE, TPB>>>(ue, ie, rows);
    lg_scan     <<<NCHUNK, SCAN_CHUNK>>>();
    lg_scatter  <<<(NNZ / 2 + TPB - 1) / TPB, TPB>>>(rows, cols, vals);

    lg_csr_spmm      <<<grid_rows, TPB>>>(h0, h1);
    lg_csr_spmm      <<<grid_rows, TPB>>>(h1, h2);
    lg_csr_spmm_final<<<grid_rows, TPB>>>(out);
}

// round 10
// speedup vs baseline: 1.0005x; 1.0005x over previous
#include <cuda_runtime.h>
#include <cuda_fp16.h>
#include <cuda_bf16.h>

#define NUM_USERS 100000
#define NUM_ITEMS 50000
#define DIM 64
#define N_TOTAL (NUM_USERS + NUM_ITEMS)
#define NNZ 4800000
#define TOT (N_TOTAL * DIM)

#define SCAN_CHUNK 1024
#define NCHUNK ((N_TOTAL + SCAN_CHUNK - 1) / SCAN_CHUNK)   // 147
#define GRID_ELEM ((TOT / 4 + 255) / 256)                   // 9375
#define GRID_EDGE ((NNZ + 255) / 256)                       // 18750

// fp16 layer embeddings (gather operands AND epilogue inputs)
__device__ __align__(16) __half g_h0[TOT];
__device__ __align__(16) __half g_h1[TOT];
__device__ __align__(16) __half g_h2[TOT];

// CSR build scratch
__device__ int g_cnt[N_TOTAL];            // zero at load; re-zeroed by lg_scan each call
__device__ int g_rowptr[N_TOTAL + 1];
__device__ int g_ofs[N_TOTAL];
__device__ unsigned long long g_state[NCHUNK];  // decoupled-lookback state
__device__ __align__(8) int2 g_cv[NNZ];   // .x = col, .y = val bits (fp32)

// ---------------------------------------------------------------------------
// fused init + hist (independent; grid-partitioned)
// ---------------------------------------------------------------------------
__global__ void __launch_bounds__(256) lg_init_hist(const float* __restrict__ ue,
                                                    const float* __restrict__ ie,
                                                    const int* __restrict__ rows) {
    if (blockIdx.x < GRID_ELEM) {
        int i = blockIdx.x * blockDim.x + threadIdx.x;
        if (blockIdx.x == 0 && threadIdx.x < NCHUNK) g_state[threadIdx.x] = 0ULL;
        if (i >= TOT / 4) return;
        const int user4 = (NUM_USERS * DIM) / 4;
        float4 v = (i < user4) ? __ldg((const float4*)ue + i)
                               : __ldg((const float4*)ie + (i - user4));
        __half2 h01 = __float22half2_rn(make_float2(v.x, v.y));
        __half2 h23 = __float22half2_rn(make_float2(v.z, v.w));
        uint2 packed = make_uint2(*(unsigned*)&h01, *(unsigned*)&h23);
        ((uint2*)g_h0)[i] = packed;
    } else {
        int e = (blockIdx.x - GRID_ELEM) * blockDim.x + threadIdx.x;
        if (e >= NNZ) return;
        atomicAdd(&g_cnt[__ldcs(rows + e)], 1);
    }
}

// ---------------------------------------------------------------------------
// Single-kernel exclusive scan (decoupled lookback, one wave on 148 SMs).
// Re-zeroes g_cnt for the next call.
// ---------------------------------------------------------------------------
__global__ void __launch_bounds__(SCAN_CHUNK) lg_scan() {
    __shared__ int ws[32];
    __shared__ int s_excl;
    const int bid = blockIdx.x;
    const int tid = threadIdx.x, lane = tid & 31, w = tid >> 5;
    const int i = bid * SCAN_CHUNK + tid;

    int v = (i < N_TOTAL) ? g_cnt[i] : 0;
    if (i < N_TOTAL) g_cnt[i] = 0;

    int inc = v;
    #pragma unroll
    for (int d = 1; d < 32; d <<= 1) {
        int t = __shfl_up_sync(0xffffffffu, inc, d);
        if (lane >= d) inc += t;
    }
    if (lane == 31) ws[w] = inc;
    __syncthreads();
    if (w == 0) {
        int s = ws[lane];
        #pragma unroll
        for (int d = 1; d < 32; d <<= 1) {
            int t = __shfl_up_sync(0xffffffffu, s, d);
            if (lane >= d) s += t;
        }
        ws[lane] = s;
    }
    __syncthreads();
    int total = ws[31];

    if (w == 0) {
        if (bid == 0) {
            if (lane == 0) {
                s_excl = 0;
                atomicExch(&g_state[0], (2ULL << 32) | (unsigned)total);
            }
        } else {
            if (lane == 0)
                atomicExch(&g_state[bid], (1ULL << 32) | (unsigned)total);
            int run = 0;
            int j = bid - 1;
            for (;;) {
                int idx = j - lane;
                unsigned long long st = (idx >= 0)
                    ? atomicAdd(&g_state[idx], 0ULL)
                    : (2ULL << 32);
                unsigned status = (unsigned)(st >> 32);
                if (__any_sync(0xffffffffu, status == 0)) continue;
                unsigned mask2 = __ballot_sync(0xffffffffu, status == 2);
                if (mask2) {
                    int firstLane = __ffs(mask2) - 1;
                    int contrib = (lane <= firstLane) ? (int)(unsigned)st : 0;
                    #pragma unroll
                    for (int d = 16; d > 0; d >>= 1)
                        contrib += __shfl_down_sync(0xffffffffu, contrib, d);
                    contrib = __shfl_sync(0xffffffffu, contrib, 0);
                    run += contrib;
                    break;
                } else {
                    int contrib = (int)(unsigned)st;
                    #pragma unroll
                    for (int d = 16; d > 0; d >>= 1)
                        contrib += __shfl_down_sync(0xffffffffu, contrib, d);
                    contrib = __shfl_sync(0xffffffffu, contrib, 0);
                    run += contrib;
                    j -= 32;
                }
            }
            if (lane == 0) {
                s_excl = run;
                atomicExch(&g_state[bid], (2ULL << 32) | (unsigned)(run + total));
            }
        }
    }
    __syncthreads();

    int excl = inc - v + (w > 0 ? ws[w - 1] : 0) + s_excl;
    if (i < N_TOTAL) { g_rowptr[i] = excl; g_ofs[i] = excl; }
    if (bid == 0 && tid == 0) g_rowptr[N_TOTAL] = NNZ;
}

// ---------------------------------------------------------------------------
__global__ void __launch_bounds__(256) lg_scatter(const int* __restrict__ rows,
                                                  const int* __restrict__ cols,
                                                  const float* __restrict__ vals) {
    int t = blockIdx.x * blockDim.x + threadIdx.x;
    if (t >= NNZ / 2) return;
    int2   r = __ldcs((const int2*)rows + t);
    int2   c = __ldcs((const int2*)cols + t);
    float2 v = __ldcs((const float2*)vals + t);
    int pos0 = atomicAdd(&g_ofs[r.x], 1);
    int pos1 = atomicAdd(&g_ofs[r.y], 1);
    __stcs(&g_cv[pos0], make_int2(c.x, __float_as_int(v.x)));
    __stcs(&g_cv[pos1], make_int2(c.y, __float_as_int(v.y)));
}

// ---------------------------------------------------------------------------
// CSR SpMM core, edge-pair scheme. Half-warp h handles edge 2p+h of each pair;
// lane owns 4 output floats (one uint2 = 2 half2 per gather). Per 2 edges:
// 1 LDG.64 + 2 SHFL (vs 2 LDG + 4 SHFL before). fp32 accumulate.
// Result must be reduced across halves (shfl_xor 16) by the caller.
// ---------------------------------------------------------------------------
__device__ __forceinline__ void pair_batch(const uint2* __restrict__ xh8,
                                           const int* cc, const float* vv,
                                           int sub,
                                           float& a0, float& a1, float& a2, float& a3) {
    uint2 xv[8];
    #pragma unroll
    for (int p = 0; p < 8; p++)
        xv[p] = __ldg(xh8 + (size_t)cc[p] * 16 + sub);
    #pragma unroll
    for (int p = 0; p < 8; p++) {
        float2 f01 = __half22float2(*(const __half2*)&xv[p].x);
        float2 f23 = __half22float2(*(const __half2*)&xv[p].y);
        a0 = fmaf(vv[p], f01.x, a0);
        a1 = fmaf(vv[p], f01.y, a1);
        a2 = fmaf(vv[p], f23.x, a2);
        a3 = fmaf(vv[p], f23.y, a3);
    }
}

__device__ __forceinline__ void spmm_row(const uint2* __restrict__ xh8,
                                         int beg, int end, int lane,
                                         float& a0, float& a1, float& a2, float& a3) {
    const int half = lane >> 4;
    const int sub  = lane & 15;
    int deg = end - beg;
    int full_end = beg + (deg & ~31);

    // full 32-edge chunks: branch-free, 2 batches of 8 pairs
    for (int j = beg; j < full_end; j += 32) {
        int2 ed = __ldcs(g_cv + j + lane);
        #pragma unroll
        for (int p0 = 0; p0 < 16; p0 += 8) {
            int cc[8]; float vv[8];
            #pragma unroll
            for (int p = 0; p < 8; p++) {
                int src = 2 * (p0 + p) + half;
                cc[p] = __shfl_sync(0xffffffffu, ed.x, src);
                vv[p] = __int_as_float(__shfl_sync(0xffffffffu, ed.y, src));
            }
            pair_batch(xh8, cc, vv, sub, a0, a1, a2, a3);
        }
    }

    // partial tail chunk: predicated pairs
    int m = end - full_end;
    if (m > 0) {
        int jj = full_end + lane;
        int2 ed = (jj < end) ? __ldcs(g_cv + jj) : make_int2(0, 0);
        int pairs = (m + 1) >> 1;
        #pragma unroll
        for (int p0 = 0; p0 < 16; p0 += 8) {
            if (p0 >= pairs) break;
            int cc[8]; float vv[8];
            #pragma unroll
            for (int p = 0; p < 8; p++) {
                int src = 2 * (p0 + p) + half;
                int   c = __shfl_sync(0xffffffffu, ed.x, src & 31);
                float v = __int_as_float(__shfl_sync(0xffffffffu, ed.y, src & 31));
                bool ok = (src < m);
                cc[p] = ok ? c : 0;
                vv[p] = ok ? v : 0.f;
            }
            pair_batch(xh8, cc, vv, sub, a0, a1, a2, a3);
        }
    }

    // combine the two half-warps (both accumulated the same output row)
    a0 += __shfl_xor_sync(0xffffffffu, a0, 16);
    a1 += __shfl_xor_sync(0xffffffffu, a1, 16);
    a2 += __shfl_xor_sync(0xffffffffu, a2, 16);
    a3 += __shfl_xor_sync(0xffffffffu, a3, 16);
}

// yh = fp16(A @ x), x fp16
__global__ void __launch_bounds__(256) lg_csr_spmm(const uint2* __restrict__ xh8,
                                                   uint2* __restrict__ yh8) {
    int gtid = blockIdx.x * blockDim.x + threadIdx.x;
    int row  = gtid >> 5;
    int lane = gtid & 31;
    if (row >= N_TOTAL) return;
    int beg = __ldg(g_rowptr + row);
    int end = __ldg(g_rowptr + row + 1);
    float a0 = 0.f, a1 = 0.f, a2 = 0.f, a3 = 0.f;
    spmm_row(xh8, beg, end, lane, a0, a1, a2, a3);
    if (lane < 16) {
        __half2 o01 = __float22half2_rn(make_float2(a0, a1));
        __half2 o23 = __float22half2_rn(make_float2(a2, a3));
        uint2 pk = make_uint2(*(unsigned*)&o01, *(unsigned*)&o23);
        yh8[(size_t)row * 16 + lane] = pk;
    }
}

// Layer 3 fused with the mean: out = 0.25 * (h0 + h1 + h2 + A@h2)
__global__ void __launch_bounds__(256) lg_csr_spmm_final(float* __restrict__ out) {
    int gtid = blockIdx.x * blockDim.x + threadIdx.x;
    int row  = gtid >> 5;
    int lane = gtid & 31;
    if (row >= N_TOTAL) return;
    int beg = __ldg(g_rowptr + row);
    int end = __ldg(g_rowptr + row + 1);
    float a0 = 0.f, a1 = 0.f, a2 = 0.f, a3 = 0.f;
    spmm_row((const uint2*)g_h2, beg, end, lane, a0, a1, a2, a3);
    if (lane < 16) {
        size_t p = (size_t)row * 16 + lane;
        uint2 u0 = __ldg((const uint2*)g_h0 + p);
        uint2 u1 = __ldg((const uint2*)g_h1 + p);
        uint2 u2 = __ldg((const uint2*)g_h2 + p);
        float2 e0a = __half22float2(*(const __half2*)&u0.x), e0b = __half22float2(*(const __half2*)&u0.y);
        float2 e1a = __half22float2(*(const __half2*)&u1.x), e1b = __half22float2(*(const __half2*)&u1.y);
        float2 e2a = __half22float2(*(const __half2*)&u2.x), e2b = __half22float2(*(const __half2*)&u2.y);
        float4 o;
        o.x = (e0a.x + e1a.x + e2a.x + a0) * 0.25f;
        o.y = (e0a.y + e1a.y + e2a.y + a1) * 0.25f;
        o.z = (e0b.x + e1b.x + e2b.x + a2) * 0.25f;
        o.w = (e0b.y + e1b.y + e2b.y + a3) * 0.25f;
        ((float4*)(out + (size_t)row * DIM))[lane] = o;
    }
}

extern "C" void kernel_launch(void* const* d_in, const int* in_sizes, int n_in,
                              void* d_out, int out_size) {
    const float* ue   = (const float*)d_in[0];
    const float* ie   = (const float*)d_in[1];
    const float* vals = (const float*)d_in[2];
    const int*   rows = (const int*)  d_in[3];
    const int*   cols = (const int*)  d_in[4];
    float* out = (float*)d_out;

    uint2 *h0, *h1, *h2;
    cudaGetSymbolAddress((void**)&h0, g_h0);
    cudaGetSymbolAddress((void**)&h1, g_h1);
    cudaGetSymbolAddress((void**)&h2, g_h2);

    const int TPB = 256;
    const int grid_rows = (N_TOTAL * 32 + TPB - 1) / TPB;

    lg_init_hist<<<GRID_ELEM + GRID_EDGE, TPB>>>(ue, ie, rows);
    lg_scan     <<<NCHUNK, SCAN_CHUNK>>>();
    lg_scatter  <<<(NNZ / 2 + TPB - 1) / TPB, TPB>>>(rows, cols, vals);

    lg_csr_spmm      <<<grid_rows, TPB>>>(h0, h1);
    lg_csr_spmm      <<<grid_rows, TPB>>>(h1, h2);
    lg_csr_spmm_final<<<grid_rows, TPB>>>(out);
}

// round 11
// speedup vs baseline: 1.0562x; 1.0556x over previous
#include <cuda_runtime.h>
#include <cuda_fp16.h>
#include <cuda_bf16.h>

#define NUM_USERS 100000
#define NUM_ITEMS 50000
#define DIM 64
#define N_TOTAL (NUM_USERS + NUM_ITEMS)
#define NNZ 4800000
#define TOT (N_TOTAL * DIM)

#define SCAN_CHUNK 1024
#define NCHUNK ((N_TOTAL + SCAN_CHUNK - 1) / SCAN_CHUNK)   // 147
#define GRID_ELEM ((TOT / 4 + 255) / 256)                   // 9375
#define GRID_EDGE ((NNZ + 255) / 256)                       // 18750

// fp16 layer embeddings (gather operands AND epilogue inputs)
__device__ __align__(16) __half g_h0[TOT];
__device__ __align__(16) __half g_h1[TOT];
__device__ __align__(16) __half g_h2[TOT];

// CSR build scratch
__device__ int g_cnt[N_TOTAL];            // zero at load; re-zeroed by lg_scan each call
__device__ int g_rowptr[N_TOTAL + 1];
__device__ int g_ofs[N_TOTAL];
__device__ unsigned long long g_state[NCHUNK];  // decoupled-lookback state
__device__ __align__(8) int2 g_cv[NNZ];   // .x = col, .y = val bits (fp32)

// ---------------------------------------------------------------------------
// fused init + hist (independent; grid-partitioned)
// ---------------------------------------------------------------------------
__global__ void __launch_bounds__(256) lg_init_hist(const float* __restrict__ ue,
                                                    const float* __restrict__ ie,
                                                    const int* __restrict__ rows) {
    if (blockIdx.x < GRID_ELEM) {
        int i = blockIdx.x * blockDim.x + threadIdx.x;
        if (blockIdx.x == 0 && threadIdx.x < NCHUNK) g_state[threadIdx.x] = 0ULL;
        if (i >= TOT / 4) return;
        const int user4 = (NUM_USERS * DIM) / 4;
        float4 v = (i < user4) ? __ldg((const float4*)ue + i)
                               : __ldg((const float4*)ie + (i - user4));
        __half2 h01 = __float22half2_rn(make_float2(v.x, v.y));
        __half2 h23 = __float22half2_rn(make_float2(v.z, v.w));
        uint2 packed = make_uint2(*(unsigned*)&h01, *(unsigned*)&h23);
        ((uint2*)g_h0)[i] = packed;
    } else {
        int e = (blockIdx.x - GRID_ELEM) * blockDim.x + threadIdx.x;
        if (e >= NNZ) return;
        atomicAdd(&g_cnt[__ldcs(rows + e)], 1);
    }
}

// ---------------------------------------------------------------------------
// Single-kernel exclusive scan (decoupled lookback, one wave on 148 SMs).
// Re-zeroes g_cnt for the next call.
// ---------------------------------------------------------------------------
__global__ void __launch_bounds__(SCAN_CHUNK) lg_scan() {
    __shared__ int ws[32];
    __shared__ int s_excl;
    const int bid = blockIdx.x;
    const int tid = threadIdx.x, lane = tid & 31, w = tid >> 5;
    const int i = bid * SCAN_CHUNK + tid;

    int v = (i < N_TOTAL) ? g_cnt[i] : 0;
    if (i < N_TOTAL) g_cnt[i] = 0;

    int inc = v;
    #pragma unroll
    for (int d = 1; d < 32; d <<= 1) {
        int t = __shfl_up_sync(0xffffffffu, inc, d);
        if (lane >= d) inc += t;
    }
    if (lane == 31) ws[w] = inc;
    __syncthreads();
    if (w == 0) {
        int s = ws[lane];
        #pragma unroll
        for (int d = 1; d < 32; d <<= 1) {
            int t = __shfl_up_sync(0xffffffffu, s, d);
            if (lane >= d) s += t;
        }
        ws[lane] = s;
    }
    __syncthreads();
    int total = ws[31];

    if (w == 0) {
        if (bid == 0) {
            if (lane == 0) {
                s_excl = 0;
                atomicExch(&g_state[0], (2ULL << 32) | (unsigned)total);
            }
        } else {
            if (lane == 0)
                atomicExch(&g_state[bid], (1ULL << 32) | (unsigned)total);
            int run = 0;
            int j = bid - 1;
            for (;;) {
                int idx = j - lane;
                unsigned long long st = (idx >= 0)
                    ? atomicAdd(&g_state[idx], 0ULL)
                    : (2ULL << 32);
                unsigned status = (unsigned)(st >> 32);
                if (__any_sync(0xffffffffu, status == 0)) continue;
                unsigned mask2 = __ballot_sync(0xffffffffu, status == 2);
                if (mask2) {
                    int firstLane = __ffs(mask2) - 1;
                    int contrib = (lane <= firstLane) ? (int)(unsigned)st : 0;
                    #pragma unroll
                    for (int d = 16; d > 0; d >>= 1)
                        contrib += __shfl_down_sync(0xffffffffu, contrib, d);
                    contrib = __shfl_sync(0xffffffffu, contrib, 0);
                    run += contrib;
                    break;
                } else {
                    int contrib = (int)(unsigned)st;
                    #pragma unroll
                    for (int d = 16; d > 0; d >>= 1)
                        contrib += __shfl_down_sync(0xffffffffu, contrib, d);
                    contrib = __shfl_sync(0xffffffffu, contrib, 0);
                    run += contrib;
                    j -= 32;
                }
            }
            if (lane == 0) {
                s_excl = run;
                atomicExch(&g_state[bid], (2ULL << 32) | (unsigned)(run + total));
            }
        }
    }
    __syncthreads();

    int excl = inc - v + (w > 0 ? ws[w - 1] : 0) + s_excl;
    if (i < N_TOTAL) { g_rowptr[i] = excl; g_ofs[i] = excl; }
    if (bid == 0 && tid == 0) g_rowptr[N_TOTAL] = NNZ;
}

// ---------------------------------------------------------------------------
__global__ void __launch_bounds__(256) lg_scatter(const int* __restrict__ rows,
                                                  const int* __restrict__ cols,
                                                  const float* __restrict__ vals) {
    int t = blockIdx.x * blockDim.x + threadIdx.x;
    if (t >= NNZ / 2) return;
    int2   r = __ldcs((const int2*)rows + t);
    int2   c = __ldcs((const int2*)cols + t);
    float2 v = __ldcs((const float2*)vals + t);
    int pos0 = atomicAdd(&g_ofs[r.x], 1);
    int pos1 = atomicAdd(&g_ofs[r.y], 1);
    __stcs(&g_cv[pos0], make_int2(c.x, __float_as_int(v.x)));
    __stcs(&g_cv[pos1], make_int2(c.y, __float_as_int(v.y)));
}

// ---------------------------------------------------------------------------
// CSR SpMM core, quarter-warp scheme. Each group of 4 edges is handled by the
// 4 quarter-warps (8 lanes each); a lane owns 8 output floats and loads one
// uint4 (16 B = 8 halves) of its edge's x row. Per 4 edges: 1 warp-LDG.128 +
// 2 per-lane-src SHFLs. fp32 accumulate in a[8]; quarters reduced at the end.
// ---------------------------------------------------------------------------
__device__ __forceinline__ void q_accum(const uint4* __restrict__ xh16,
                                        int c, float v, int sub, float* a) {
    uint4 xv = __ldg(xh16 + (size_t)c * 8 + sub);
    float2 f0 = __half22float2(*(const __half2*)&xv.x);
    float2 f1 = __half22float2(*(const __half2*)&xv.y);
    float2 f2 = __half22float2(*(const __half2*)&xv.z);
    float2 f3 = __half22float2(*(const __half2*)&xv.w);
    a[0] = fmaf(v, f0.x, a[0]); a[1] = fmaf(v, f0.y, a[1]);
    a[2] = fmaf(v, f1.x, a[2]); a[3] = fmaf(v, f1.y, a[3]);
    a[4] = fmaf(v, f2.x, a[4]); a[5] = fmaf(v, f2.y, a[5]);
    a[6] = fmaf(v, f3.x, a[6]); a[7] = fmaf(v, f3.y, a[7]);
}

__device__ __forceinline__ void spmm_row(const uint4* __restrict__ xh16,
                                         int beg, int end, int lane, float* a) {
    const int q   = lane >> 3;   // quarter id: which edge of each 4-group
    const int sub = lane & 7;    // which uint4 of the 64-half row
    int deg = end - beg;
    int full_end = beg + (deg & ~31);

    // full 32-edge chunks: 8 groups of 4 edges, branch-free
    for (int j = beg; j < full_end; j += 32) {
        int2 ed = __ldcs(g_cv + j + lane);
        #pragma unroll
        for (int g = 0; g < 8; g++) {
            int src = 4 * g + q;
            int   c = __shfl_sync(0xffffffffu, ed.x, src);
            float v = __int_as_float(__shfl_sync(0xffffffffu, ed.y, src));
            q_accum(xh16, c, v, sub, a);
        }
    }

    // partial tail chunk: predicated groups
    int m = end - full_end;
    if (m > 0) {
        int jj = full_end + lane;
        int2 ed = (jj < end) ? __ldcs(g_cv + jj) : make_int2(0, 0);
        int groups = (m + 3) >> 2;
        #pragma unroll
        for (int g = 0; g < 8; g++) {
            if (g >= groups) break;
            int src = 4 * g + q;
            int   c = __shfl_sync(0xffffffffu, ed.x, src);
            float v = __int_as_float(__shfl_sync(0xffffffffu, ed.y, src));
            bool ok = (src < m);
            q_accum(xh16, ok ? c : 0, ok ? v : 0.f, sub, a);
        }
    }

    // reduce the 4 quarter-warps (same output row, different edges)
    #pragma unroll
    for (int k = 0; k < 8; k++) {
        a[k] += __shfl_xor_sync(0xffffffffu, a[k], 8);
        a[k] += __shfl_xor_sync(0xffffffffu, a[k], 16);
    }
}

// yh = fp16(A @ x), x fp16
__global__ void __launch_bounds__(256) lg_csr_spmm(const uint4* __restrict__ xh16,
                                                   uint4* __restrict__ yh16) {
    int gtid = blockIdx.x * blockDim.x + threadIdx.x;
    int row  = gtid >> 5;
    int lane = gtid & 31;
    if (row >= N_TOTAL) return;
    int beg = __ldg(g_rowptr + row);
    int end = __ldg(g_rowptr + row + 1);
    float a[8] = {0.f, 0.f, 0.f, 0.f, 0.f, 0.f, 0.f, 0.f};
    spmm_row(xh16, beg, end, lane, a);
    if (lane < 8) {
        __half2 p0 = __float22half2_rn(make_float2(a[0], a[1]));
        __half2 p1 = __float22half2_rn(make_float2(a[2], a[3]));
        __half2 p2 = __float22half2_rn(make_float2(a[4], a[5]));
        __half2 p3 = __float22half2_rn(make_float2(a[6], a[7]));
        uint4 pk = make_uint4(*(unsigned*)&p0, *(unsigned*)&p1,
                              *(unsigned*)&p2, *(unsigned*)&p3);
        yh16[(size_t)row * 8 + lane] = pk;
    }
}

// Layer 3 fused with the mean: out = 0.25 * (h0 + h1 + h2 + A@h2)
__global__ void __launch_bounds__(256) lg_csr_spmm_final(float* __restrict__ out) {
    int gtid = blockIdx.x * blockDim.x + threadIdx.x;
    int row  = gtid >> 5;
    int lane = gtid & 31;
    if (row >= N_TOTAL) return;
    int beg = __ldg(g_rowptr + row);
    int end = __ldg(g_rowptr + row + 1);
    float a[8] = {0.f, 0.f, 0.f, 0.f, 0.f, 0.f, 0.f, 0.f};
    spmm_row((const uint4*)g_h2, beg, end, lane, a);
    if (lane < 8) {
        size_t p = (size_t)row * 8 + lane;
        uint4 u0 = __ldg((const uint4*)g_h0 + p);
        uint4 u1 = __ldg((const uint4*)g_h1 + p);
        uint4 u2 = __ldg((const uint4*)g_h2 + p);
        float o[8];
        const unsigned* pu0 = &u0.x;
        const unsigned* pu1 = &u1.x;
        const unsigned* pu2 = &u2.x;
        #pragma unroll
        for (int k = 0; k < 4; k++) {
            float2 e0 = __half22float2(*(const __half2*)&pu0[k]);
            float2 e1 = __half22float2(*(const __half2*)&pu1[k]);
            float2 e2 = __half22float2(*(const __half2*)&pu2[k]);
            o[2*k]   = (e0.x + e1.x + e2.x + a[2*k])   * 0.25f;
            o[2*k+1] = (e0.y + e1.y + e2.y + a[2*k+1]) * 0.25f;
        }
        float4* dst = (float4*)(out + (size_t)row * DIM + lane * 8);
        dst[0] = make_float4(o[0], o[1], o[2], o[3]);
        dst[1] = make_float4(o[4], o[5], o[6], o[7]);
    }
}

extern "C" void kernel_launch(void* const* d_in, const int* in_sizes, int n_in,
                              void* d_out, int out_size) {
    const float* ue   = (const float*)d_in[0];
    const float* ie   = (const float*)d_in[1];
    const float* vals = (const float*)d_in[2];
    const int*   rows = (const int*)  d_in[3];
    const int*   cols = (const int*)  d_in[4];
    float* out = (float*)d_out;

    uint4 *h0, *h1, *h2;
    cudaGetSymbolAddress((void**)&h0, g_h0);
    cudaGetSymbolAddress((void**)&h1, g_h1);
    cudaGetSymbolAddress((void**)&h2, g_h2);

    const int TPB = 256;
    const int grid_rows = (N_TOTAL * 32 + TPB - 1) / TPB;

    lg_init_hist<<<GRID_ELEM + GRID_EDGE, TPB>>>(ue, ie, rows);
    lg_scan     <<<NCHUNK, SCAN_CHUNK>>>();
    lg_scatter  <<<(NNZ / 2 + TPB - 1) / TPB, TPB>>>(rows, cols, vals);

    lg_csr_spmm      <<<grid_rows, TPB>>>(h0, h1);
    lg_csr_spmm      <<<grid_rows, TPB>>>(h1, h2);
    lg_csr_spmm_final<<<grid_rows, TPB>>>(out);
}